// round 15
// baseline (speedup 1.0000x reference)
#include <cuda_runtime.h>
#include <cuda_fp16.h>
#include <cuda_bf16.h>
#include <cstdint>
#include <math.h>

#define BATCH 512
#define NSEQ  128
#define DDIM  128
#define BIGF 1e30f

#define NCTA  296           // 2 CTAs per SM (148 SMs)
#define NDIAG 255           // 2*NSEQ-1
#define KPAD  31            // pad rows before/after the 255 diagonals (inf-filled)
#define NROWS (NDIAG + 2 * KPAD)               // 317
#define PH    136           // bf16 staging pitch in halves (272 B/row; ldmatrix conflict-free)
#define DP_H  136           // diag pitch in halves (proven conflict-free)
#define BUF_WORDS (NSEQ * PH)                  // per-matrix halves = 17408
#define SM_DYN_BYTES (NROWS * DP_H * 2)        // 86224 B (staging 69632 B overlays start)
#define FILL_U4 (NROWS * DP_H * 2 / 16)        // 5389 uint4

__device__ float g_dtw[BATCH];
__device__ int   g_ctr = 0;

__device__ __forceinline__ uint32_t smem_u32(const void* p) {
    uint32_t a;
    asm("{ .reg .u64 t; cvta.to.shared.u64 t, %1; cvt.u32.u64 %0, t; }" : "=r"(a) : "l"(p));
    return a;
}
__device__ __forceinline__ uint32_t f22bf(float lo, float hi) {
    uint32_t r;
    asm("cvt.rn.bf16x2.f32 %0, %1, %2;" : "=r"(r) : "f"(hi), "f"(lo));
    return r;
}
__device__ __forceinline__ float2 bf22f2(uint32_t u) {
    __nv_bfloat162 h = *(__nv_bfloat162*)&u;
    return __bfloat1622float2(h);
}
__device__ __forceinline__ void ldmx4(uint32_t* r, uint32_t addr) {
    asm volatile("ldmatrix.sync.aligned.m8n8.x4.shared.b16 {%0,%1,%2,%3}, [%4];"
                 : "=r"(r[0]), "=r"(r[1]), "=r"(r[2]), "=r"(r[3]) : "r"(addr));
}
__device__ __forceinline__ void mma_bf16(float c[4], const uint32_t a[4],
                                         const uint32_t b[2]) {
    asm volatile(
        "mma.sync.aligned.m16n8k16.row.col.f32.bf16.bf16.f32 "
        "{%0,%1,%2,%3}, {%4,%5,%6,%7}, {%8,%9}, {%0,%1,%2,%3};\n"
        : "+f"(c[0]), "+f"(c[1]), "+f"(c[2]), "+f"(c[3])
        : "r"(a[0]), "r"(a[1]), "r"(a[2]), "r"(a[3]), "r"(b[0]), "r"(b[1]));
}

__global__ __launch_bounds__(256, 2) void fused_kernel(const float* __restrict__ X,
                                                       const float* __restrict__ Y,
                                                       float* __restrict__ out) {
    extern __shared__ __align__(16) __nv_bfloat16 smh[];
    __shared__ float xxs[NSEQ], yys[NSEQ];
    __shared__ float s_bval[3][288];   // warp-boundary R values, indexed by producer step
    __shared__ int   s_cnt[3];         // last completed producer step

    const int tid = threadIdx.x, w = tid >> 5, lane = tid & 31;
    const int c = blockIdx.x;
    const int nb = (c < BATCH - NCTA) ? 2 : 1;      // c<216 -> 2 batches

    const int qr = lane >> 2, qc = lane & 3;
    const int m0 = (w & 1) * 64, n0 = (w >> 1) * 32;

    __nv_bfloat16* Xs = smh;                 // [128][136] bf16 (overlays D rows 0..)
    __nv_bfloat16* Ys = smh + BUF_WORDS;     // [128][136] bf16
    __half* Dd = (__half*)smh;               // [317][136] fp16 (diag k at row k+31)

    // ldmatrix source addresses (constant across k; add 2*k0 bytes per step)
    const uint32_t xs_a = smem_u32(Xs);
    uint32_t aAddr[4], bAddr[2];
    #pragma unroll
    for (int mt = 0; mt < 4; mt++)
        aAddr[mt] = xs_a + (uint32_t)(((m0 + mt * 16 + (lane & 15)) * PH + (lane >> 4) * 8) * 2);
    const uint32_t ys_a = smem_u32(Ys);
    #pragma unroll
    for (int j = 0; j < 2; j++)
        bAddr[j] = ys_a + (uint32_t)(((n0 + (2 * j + (lane >> 4)) * 8 + (lane & 7)) * PH
                                      + ((lane >> 3) & 1) * 8) * 2);

    for (int ib = 0; ib < nb; ib++) {
        const int b = c + ib * NCTA;

        // ---- stage FULL X,Y as bf16 (deep-MLP coalesced LDG.128) ----
        const float* Xg = X + (size_t)b * NSEQ * DDIM;
        const float* Yg = Y + (size_t)b * NSEQ * DDIM;
        #pragma unroll 8
        for (int s = 0; s < 16; s++) {
            int idx = s * 256 + tid;            // 0..4095 float4s
            int r = idx >> 5, c4 = (idx & 31) << 2;
            float4 xv = *(const float4*)(Xg + r * DDIM + c4);
            float4 yv = *(const float4*)(Yg + r * DDIM + c4);
            *(uint2*)&Xs[r * PH + c4] = make_uint2(f22bf(xv.x, xv.y), f22bf(xv.z, xv.w));
            *(uint2*)&Ys[r * PH + c4] = make_uint2(f22bf(yv.x, yv.y), f22bf(yv.z, yv.w));
        }
        __syncthreads();

        // ---- norms from bf16 smem (1 row per thread) ----
        {
            int r = tid & 127;
            const __nv_bfloat16* src = (tid < NSEQ) ? Xs : Ys;
            float s = 0.f;
            #pragma unroll
            for (int cc = 0; cc < DDIM; cc += 8) {
                uint4 v = *(const uint4*)&src[r * PH + cc];
                float2 f0 = bf22f2(v.x), f1 = bf22f2(v.y);
                float2 f2 = bf22f2(v.z), f3 = bf22f2(v.w);
                s = fmaf(f0.x, f0.x, fmaf(f0.y, f0.y, s));
                s = fmaf(f1.x, f1.x, fmaf(f1.y, f1.y, s));
                s = fmaf(f2.x, f2.x, fmaf(f2.y, f2.y, s));
                s = fmaf(f3.x, f3.x, fmaf(f3.y, f3.y, s));
            }
            if (tid < NSEQ) xxs[r] = s; else yys[r] = s;
        }

        // ---- bf16 HMMA mainloop: 8 K-steps of 16, fragments via ldmatrix.x4 ----
        float acc[4][4][4];
        #pragma unroll
        for (int mt = 0; mt < 4; mt++)
            #pragma unroll
            for (int nt = 0; nt < 4; nt++)
                #pragma unroll
                for (int r = 0; r < 4; r++) acc[mt][nt][r] = 0.f;

        #pragma unroll 2
        for (int k0 = 0; k0 < DDIM; k0 += 16) {
            uint32_t aF[4][4], bP[2][4];
            #pragma unroll
            for (int mt = 0; mt < 4; mt++) ldmx4(aF[mt], aAddr[mt] + 2 * k0);
            #pragma unroll
            for (int j = 0; j < 2; j++)    ldmx4(bP[j], bAddr[j] + 2 * k0);
            #pragma unroll
            for (int mt = 0; mt < 4; mt++) {
                mma_bf16(acc[mt][0], aF[mt], &bP[0][0]);
                mma_bf16(acc[mt][1], aF[mt], &bP[0][2]);
                mma_bf16(acc[mt][2], aF[mt], &bP[1][0]);
                mma_bf16(acc[mt][3], aF[mt], &bP[1][2]);
            }
        }
        __syncthreads();   // staging reads done; buffer reusable; norms visible

        // ---- fill ALL 317 diag rows with fp16 +inf; init handoff counters ----
        {
            uint4 inf4 = make_uint4(0x7C007C00u, 0x7C007C00u, 0x7C007C00u, 0x7C007C00u);
            uint4* bv = (uint4*)smh;
            for (int i = tid; i < FILL_U4; i += 256) bv[i] = inf4;
            if (tid < 3) s_cnt[tid] = -1;
        }
        __syncthreads();

        // ---- epilogue: D = xx + yy - 2*xy -> fp16, diag-major (row = k + 31) ----
        #pragma unroll
        for (int mt = 0; mt < 4; mt++) {
            int i0 = m0 + mt * 16 + qr;
            float xv0 = xxs[i0], xv1 = xxs[i0 + 8];
            #pragma unroll
            for (int nt = 0; nt < 4; nt++) {
                int j0 = n0 + nt * 8 + 2 * qc;
                float yv0 = yys[j0], yv1 = yys[j0 + 1];
                const float* cA = acc[mt][nt];
                Dd[(i0 + j0 + KPAD)     * DP_H + j0]     = __float2half(xv0 + yv0 - 2.f * cA[0]);
                Dd[(i0 + j0 + 1 + KPAD) * DP_H + j0 + 1] = __float2half(xv0 + yv1 - 2.f * cA[1]);
                Dd[(i0 + 8 + j0 + KPAD)     * DP_H + j0]     = __float2half(xv1 + yv0 - 2.f * cA[2]);
                Dd[(i0 + 8 + j0 + 1 + KPAD) * DP_H + j0 + 1] = __float2half(xv1 + yv1 - 2.f * cA[3]);
            }
        }
        __syncthreads();

        // ---- soft-DTW DP: 4 warps, 1 column per lane, skewed wavefront.
        //      lane l of warp w owns column j = 32w+l; at step s it handles
        //      diagonal k = s - l (pad rows make out-of-range reads +inf).
        //      Cross-warp boundary via s_bval/s_cnt (release/acquire).
        //      Producer (lane 31 of warp w-1) stores bv[s_p] = R[s_p-31][32w-1];
        //      consumer needs, for use at step s+1, R[s][32w-1] = bv[s+31]. ----
        if (w < 4) {
            const int l = lane;
            const bool prod = (w < 3) && (l == 31);
            const __half* dp = Dd + (KPAD - l) * DP_H + (32 * w + l);
            float p  = BIGF;                    // own col, k-1
            float u1 = BIGF;                    // col j-1, k-1
            float u2 = (w == 0 && l == 0) ? 0.f : BIGF;   // col j-1, k-2 (0 seeds R[0][0])
            const uint32_t cnt_rd = smem_u32(&s_cnt[(w > 0) ? w - 1 : 0]);
            const uint32_t cnt_wr = smem_u32(&s_cnt[(w < 3) ? w : 0]);
            const float* bv_rd = s_bval[(w > 0) ? w - 1 : 0];
            float* bv_wr = s_bval[(w < 3) ? w : 0];

            #pragma unroll 2
            for (int s = 0; s < 286; s++) {
                float recv = __shfl_up_sync(0xffffffffu, p, 1);
                float d0 = __half2float(*dp);
                float Rn = d0 + fminf(fminf(u1, u2), p);
                float h = BIGF;
                if (w > 0 && l == 0) {
                    int need = s + 31;          // producer step for R[s][32w-1] (used at s+1)
                    if (need <= 285) {
                        int cv;
                        do {
                            asm volatile("ld.acquire.cta.shared.s32 %0, [%1];"
                                         : "=r"(cv) : "r"(cnt_rd));
                        } while (cv < need);
                        h = bv_rd[need];
                    }
                }
                u2 = u1;
                u1 = (l == 0) ? h : recv;
                p = Rn;
                if (prod) {
                    bv_wr[s] = Rn;
                    asm volatile("st.release.cta.shared.s32 [%0], %1;"
                                 :: "r"(cnt_wr), "r"(s) : "memory");
                }
                dp += DP_H;
            }
            if (w == 3 && l == 31) {
                g_dtw[b] = p;                  // R[254][127]
                __threadfence();
            }
        }
        __syncthreads();   // DP done; buffer free for next batch
    }

    if (tid == 0) {
        __threadfence();
        if (atomicAdd(&g_ctr, 1) == NCTA - 1) {
            __threadfence();
            // deterministic fixed-order reduction of g_dtw[0..511]
            float a0 = 0.f, a1 = 0.f, a2 = 0.f, a3 = 0.f;
            float a4 = 0.f, a5 = 0.f, a6 = 0.f, a7 = 0.f;
            for (int i = 0; i < BATCH; i += 32) {
                float4 v0 = *(const float4*)&g_dtw[i];
                float4 v1 = *(const float4*)&g_dtw[i + 4];
                float4 v2 = *(const float4*)&g_dtw[i + 8];
                float4 v3 = *(const float4*)&g_dtw[i + 12];
                float4 v4 = *(const float4*)&g_dtw[i + 16];
                float4 v5 = *(const float4*)&g_dtw[i + 20];
                float4 v6 = *(const float4*)&g_dtw[i + 24];
                float4 v7 = *(const float4*)&g_dtw[i + 28];
                a0 += (v0.x + v0.y) + (v0.z + v0.w);
                a1 += (v1.x + v1.y) + (v1.z + v1.w);
                a2 += (v2.x + v2.y) + (v2.z + v2.w);
                a3 += (v3.x + v3.y) + (v3.z + v3.w);
                a4 += (v4.x + v4.y) + (v4.z + v4.w);
                a5 += (v5.x + v5.y) + (v5.z + v5.w);
                a6 += (v6.x + v6.y) + (v6.z + v6.w);
                a7 += (v7.x + v7.y) + (v7.z + v7.w);
            }
            float s = ((a0 + a1) + (a2 + a3)) + ((a4 + a5) + (a6 + a7));
            float E = s * (1.0f / (float)BATCH);
            out[0] = E;
            out[1] = 10.0f * sqrtf(E + 1e-10f);
            g_ctr = 0;   // reset for graph replay
        }
    }
}

extern "C" void kernel_launch(void* const* d_in, const int* in_sizes, int n_in,
                              void* d_out, int out_size) {
    const float* X = (const float*)d_in[0];   // outputs
    const float* Y = (const float*)d_in[1];   // targets
    float* out = (float*)d_out;

    cudaFuncSetAttribute(fused_kernel, cudaFuncAttributeMaxDynamicSharedMemorySize,
                         SM_DYN_BYTES);

    fused_kernel<<<NCTA, 256, SM_DYN_BYTES>>>(X, Y, out);
}

// round 16
// speedup vs baseline: 5.1668x; 5.1668x over previous
#include <cuda_runtime.h>
#include <cuda_fp16.h>
#include <cuda_bf16.h>
#include <cstdint>
#include <math.h>

#define BATCH 512
#define NSEQ  128
#define DDIM  128
#define BIGF 1e30f

#define NCTA  296           // 2 CTAs per SM
#define NDIAG 255           // 2*NSEQ-1
#define DP_H  136           // diag pitch in halves (proven conflict-free)
#define PH2   72            // bf16 staging pitch in halves (144 B/row, K-half = 64 cols)
#define SOFF  69632         // byte offset of staging region (D = 69360 B, rounded up)
#define SM_DYN_BYTES (SOFF + 2 * NSEQ * PH2 * 2)   // 69632 + 36864 = 106496 B

// Named barriers: 1 = EMPTY (DP->MMA, 32 arrive + 256 sync), 2 = FULL
// (MMA->DP, 256 arrive + 32 sync), 7 = MMA-internal (256), 3 = terminal (288).

__device__ float g_dtw[BATCH];
__device__ int   g_ctr = 0;

__device__ __forceinline__ void barsync(int id, int cnt) {
    asm volatile("bar.sync %0, %1;" :: "r"(id), "r"(cnt) : "memory");
}
__device__ __forceinline__ void bararrive(int id, int cnt) {
    asm volatile("bar.arrive %0, %1;" :: "r"(id), "r"(cnt) : "memory");
}
__device__ __forceinline__ uint32_t smem_u32(const void* p) {
    uint32_t a;
    asm("{ .reg .u64 t; cvta.to.shared.u64 t, %1; cvt.u32.u64 %0, t; }" : "=r"(a) : "l"(p));
    return a;
}
__device__ __forceinline__ uint32_t f22bf(float lo, float hi) {
    uint32_t r;
    asm("cvt.rn.bf16x2.f32 %0, %1, %2;" : "=r"(r) : "f"(hi), "f"(lo));
    return r;
}
__device__ __forceinline__ float2 bf22f2(uint32_t u) {
    __nv_bfloat162 h = *(__nv_bfloat162*)&u;
    return __bfloat1622float2(h);
}
__device__ __forceinline__ void ldmx4(uint32_t* r, uint32_t addr) {
    asm volatile("ldmatrix.sync.aligned.m8n8.x4.shared.b16 {%0,%1,%2,%3}, [%4];"
                 : "=r"(r[0]), "=r"(r[1]), "=r"(r[2]), "=r"(r[3]) : "r"(addr));
}
__device__ __forceinline__ void mma_bf16(float c[4], const uint32_t a[4],
                                         const uint32_t b[2]) {
    asm volatile(
        "mma.sync.aligned.m16n8k16.row.col.f32.bf16.bf16.f32 "
        "{%0,%1,%2,%3}, {%4,%5,%6,%7}, {%8,%9}, {%0,%1,%2,%3};\n"
        : "+f"(c[0]), "+f"(c[1]), "+f"(c[2]), "+f"(c[3])
        : "r"(a[0]), "r"(a[1]), "r"(a[2]), "r"(a[3]), "r"(b[0]), "r"(b[1]));
}

__global__ __launch_bounds__(288, 2) void fused_kernel(const float* __restrict__ X,
                                                       const float* __restrict__ Y,
                                                       float* __restrict__ out) {
    extern __shared__ __align__(16) char smraw[];
    __half* Dd = (__half*)smraw;                           // [255][136] fp16
    __nv_bfloat16* Xs = (__nv_bfloat16*)(smraw + SOFF);    // [128][72] bf16 (K-half)
    __nv_bfloat16* Ys = Xs + NSEQ * PH2;                   // [128][72] bf16
    __shared__ float xxs[NSEQ], yys[NSEQ];

    const int tid = threadIdx.x, w = tid >> 5, lane = tid & 31;
    const int c = blockIdx.x;
    const int nb = (c < BATCH - NCTA) ? 2 : 1;
    const int wdp = (c >> 1) & 7;     // DP warp; staggers SMSP across co-resident CTAs

    if (w == wdp) {
        // ===================== DP role (one warp) =====================
        bararrive(1, 288);            // initial EMPTY: buffer free for batch 0
        const int l = lane;
        for (int ib = 0; ib < nb; ib++) {
            const int b = c + ib * NCTA;
            barsync(2, 288);          // FULL: D(b) ready

            float A0 = BIGF, A1 = BIGF, A2 = BIGF, A3 = BIGF;
            float B0 = BIGF, B1 = BIGF, B2 = BIGF, B3 = BIGF;
            float uE = BIGF, uO = BIGF;
            const int zstep = (l == 0) ? 0 : -1;

            const __half* base = (const __half*)Dd + 4 * l;
            auto ldD = [&](int s_) -> uint2 {
                int k = s_ - l;
                k = k < 0 ? 0 : (k > NDIAG - 1 ? NDIAG - 1 : k);
                return *(const uint2*)(base + k * DP_H);
            };
            uint2 q0 = ldD(0), q1 = ldD(1);

            #pragma unroll 1
            for (int s = 0; s < 286; s += 2) {
                float recv = __shfl_up_sync(0xffffffffu, A3, 1);
                recv = (l == 0) ? BIGF : recv;
                uint2 dq = q0; q0 = ldD(s + 2);
                float2 f01 = __half22float2(*(__half2*)&dq.x);
                float2 f23 = __half22float2(*(__half2*)&dq.y);
                {
                    float dg0 = (s == zstep) ? 0.f : uE;
                    float t0 = f01.x + fminf(fminf(dg0, uO), A0);
                    float t1 = f01.y + fminf(fminf(B0, A0), A1);
                    float t2 = f23.x + fminf(fminf(B1, A1), A2);
                    float t3 = f23.y + fminf(fminf(B2, A2), A3);
                    B0 = t0; B1 = t1; B2 = t2; B3 = t3;
                }
                uE = recv;

                recv = __shfl_up_sync(0xffffffffu, B3, 1);
                recv = (l == 0) ? BIGF : recv;
                dq = q1; q1 = ldD(s + 3);
                f01 = __half22float2(*(__half2*)&dq.x);
                f23 = __half22float2(*(__half2*)&dq.y);
                {
                    float t0 = f01.x + fminf(fminf(uO, uE), B0);
                    float t1 = f01.y + fminf(fminf(A0, B0), B1);
                    float t2 = f23.x + fminf(fminf(A1, B1), B2);
                    float t3 = f23.y + fminf(fminf(A2, B2), B3);
                    A0 = t0; A1 = t1; A2 = t2; A3 = t3;
                }
                uO = recv;
            }
            if (l == 31) g_dtw[b] = A3;    // R[127][127] (k = 254)

            if (ib + 1 < nb) bararrive(1, 288);   // EMPTY: D buffer free
        }
        if (l == 31) {
            __threadfence();
            if (atomicAdd(&g_ctr, 1) == NCTA - 1) {
                __threadfence();
                float a0 = 0.f, a1 = 0.f, a2 = 0.f, a3 = 0.f;
                float a4 = 0.f, a5 = 0.f, a6 = 0.f, a7 = 0.f;
                for (int i = 0; i < BATCH; i += 32) {
                    float4 v0 = *(const float4*)&g_dtw[i];
                    float4 v1 = *(const float4*)&g_dtw[i + 4];
                    float4 v2 = *(const float4*)&g_dtw[i + 8];
                    float4 v3 = *(const float4*)&g_dtw[i + 12];
                    float4 v4 = *(const float4*)&g_dtw[i + 16];
                    float4 v5 = *(const float4*)&g_dtw[i + 20];
                    float4 v6 = *(const float4*)&g_dtw[i + 24];
                    float4 v7 = *(const float4*)&g_dtw[i + 28];
                    a0 += (v0.x + v0.y) + (v0.z + v0.w);
                    a1 += (v1.x + v1.y) + (v1.z + v1.w);
                    a2 += (v2.x + v2.y) + (v2.z + v2.w);
                    a3 += (v3.x + v3.y) + (v3.z + v3.w);
                    a4 += (v4.x + v4.y) + (v4.z + v4.w);
                    a5 += (v5.x + v5.y) + (v5.z + v5.w);
                    a6 += (v6.x + v6.y) + (v6.z + v6.w);
                    a7 += (v7.x + v7.y) + (v7.z + v7.w);
                }
                float s = ((a0 + a1) + (a2 + a3)) + ((a4 + a5) + (a6 + a7));
                float E = s * (1.0f / (float)BATCH);
                out[0] = E;
                out[1] = 10.0f * sqrtf(E + 1e-10f);
                g_ctr = 0;   // reset for graph replay
            }
        }
        barsync(3, 288);   // terminal rendezvous
    } else {
        // ===================== MMA role (8 warps) =====================
        const int wslot = (w == 8) ? wdp : w;         // warp 8 takes DP warp's tile
        const int qr = lane >> 2, qc = lane & 3;
        const int m0 = (wslot & 1) * 64, n0 = (wslot >> 1) * 32;
        const int mtid = tid - (w > wdp ? 32 : 0);    // rank among 256 MMA threads

        uint32_t aAddr[4], bAddr[2];
        const uint32_t xs_a = smem_u32(Xs), ys_a = smem_u32(Ys);
        #pragma unroll
        for (int mt = 0; mt < 4; mt++)
            aAddr[mt] = xs_a + (uint32_t)(((m0 + mt * 16 + (lane & 15)) * PH2
                                           + (lane >> 4) * 8) * 2);
        #pragma unroll
        for (int j = 0; j < 2; j++)
            bAddr[j] = ys_a + (uint32_t)(((n0 + (2 * j + (lane >> 4)) * 8 + (lane & 7)) * PH2
                                          + ((lane >> 3) & 1) * 8) * 2);

        for (int ib = 0; ib < nb; ib++) {
            const int b = c + ib * NCTA;
            const float* Xg = X + (size_t)b * NSEQ * DDIM;
            const float* Yg = Y + (size_t)b * NSEQ * DDIM;

            float acc[4][4][4];
            #pragma unroll
            for (int mt = 0; mt < 4; mt++)
                #pragma unroll
                for (int nt = 0; nt < 4; nt++)
                    #pragma unroll
                    for (int r = 0; r < 4; r++) acc[mt][nt][r] = 0.f;
            float nrm = 0.f;

            #pragma unroll
            for (int h = 0; h < 2; h++) {
                // ---- stage K-half h (overlaps DP(b-1): writes staging, not D) ----
                #pragma unroll 8
                for (int s = 0; s < 8; s++) {
                    int idx = s * 256 + mtid;          // 0..2047
                    int r = idx >> 4, c4 = (idx & 15) << 2;
                    float4 xv = *(const float4*)(Xg + r * DDIM + h * 64 + c4);
                    float4 yv = *(const float4*)(Yg + r * DDIM + h * 64 + c4);
                    *(uint2*)&Xs[r * PH2 + c4] = make_uint2(f22bf(xv.x, xv.y), f22bf(xv.z, xv.w));
                    *(uint2*)&Ys[r * PH2 + c4] = make_uint2(f22bf(yv.x, yv.y), f22bf(yv.z, yv.w));
                }
                barsync(7, 256);

                // ---- norm partials on this half ----
                {
                    int r = mtid & 127;
                    const __nv_bfloat16* src = (mtid < NSEQ) ? Xs : Ys;
                    float s_ = 0.f;
                    #pragma unroll
                    for (int cc = 0; cc < 64; cc += 8) {
                        uint4 v = *(const uint4*)&src[r * PH2 + cc];
                        float2 f0 = bf22f2(v.x), f1 = bf22f2(v.y);
                        float2 f2 = bf22f2(v.z), f3 = bf22f2(v.w);
                        s_ = fmaf(f0.x, f0.x, fmaf(f0.y, f0.y, s_));
                        s_ = fmaf(f1.x, f1.x, fmaf(f1.y, f1.y, s_));
                        s_ = fmaf(f2.x, f2.x, fmaf(f2.y, f2.y, s_));
                        s_ = fmaf(f3.x, f3.x, fmaf(f3.y, f3.y, s_));
                    }
                    nrm += s_;
                }

                // ---- bf16 HMMA: 4 K-steps of 16 on this half.
                //      Register-lean: bP (8 regs) live across mt loop; aF (4
                //      regs) transient per tile -> fits the 96-reg cap, no spills. ----
                #pragma unroll
                for (int k0 = 0; k0 < 64; k0 += 16) {
                    uint32_t bP[2][4];
                    ldmx4(bP[0], bAddr[0] + 2 * k0);
                    ldmx4(bP[1], bAddr[1] + 2 * k0);
                    #pragma unroll
                    for (int mt = 0; mt < 4; mt++) {
                        uint32_t aF[4];
                        ldmx4(aF, aAddr[mt] + 2 * k0);
                        mma_bf16(acc[mt][0], aF, &bP[0][0]);
                        mma_bf16(acc[mt][1], aF, &bP[0][2]);
                        mma_bf16(acc[mt][2], aF, &bP[1][0]);
                        mma_bf16(acc[mt][3], aF, &bP[1][2]);
                    }
                }
                if (h == 0) barsync(7, 256);   // half0 reads done before restaging
            }

            if (mtid < NSEQ) xxs[mtid & 127] = nrm; else yys[mtid & 127] = nrm;

            barsync(1, 288);   // EMPTY: wait DP(b-1) done with D region

            // ---- fill D with fp16 +inf (invalid cells self-mask in DP) ----
            {
                uint4 inf4 = make_uint4(0x7C007C00u, 0x7C007C00u, 0x7C007C00u, 0x7C007C00u);
                uint4* bv = (uint4*)smraw;
                #pragma unroll
                for (int i = mtid; i < NDIAG * DP_H * 2 / 16; i += 256) bv[i] = inf4;
            }
            barsync(7, 256);

            // ---- epilogue: D = xx + yy - 2*xy -> fp16, diag-major ----
            #pragma unroll
            for (int mt = 0; mt < 4; mt++) {
                int i0 = m0 + mt * 16 + qr;
                float xv0 = xxs[i0], xv1 = xxs[i0 + 8];
                #pragma unroll
                for (int nt = 0; nt < 4; nt++) {
                    int j0 = n0 + nt * 8 + 2 * qc;
                    float yv0 = yys[j0], yv1 = yys[j0 + 1];
                    const float* cA = acc[mt][nt];
                    Dd[(i0 + j0)         * DP_H + j0]     = __float2half(xv0 + yv0 - 2.f * cA[0]);
                    Dd[(i0 + j0 + 1)     * DP_H + j0 + 1] = __float2half(xv0 + yv1 - 2.f * cA[1]);
                    Dd[(i0 + 8 + j0)     * DP_H + j0]     = __float2half(xv1 + yv0 - 2.f * cA[2]);
                    Dd[(i0 + 8 + j0 + 1) * DP_H + j0 + 1] = __float2half(xv1 + yv1 - 2.f * cA[3]);
                }
            }
            bararrive(2, 288);   // FULL: D(b) ready; proceed to stage b+1 under DP(b)
        }
        barsync(3, 288);   // terminal rendezvous
    }
}

extern "C" void kernel_launch(void* const* d_in, const int* in_sizes, int n_in,
                              void* d_out, int out_size) {
    const float* X = (const float*)d_in[0];   // outputs
    const float* Y = (const float*)d_in[1];   // targets
    float* out = (float*)d_out;

    cudaFuncSetAttribute(fused_kernel, cudaFuncAttributeMaxDynamicSharedMemorySize,
                         SM_DYN_BYTES);

    fused_kernel<<<NCTA, 288, SM_DYN_BYTES>>>(X, Y, out);
}

// round 17
// speedup vs baseline: 6.5473x; 1.2672x over previous
#include <cuda_runtime.h>
#include <cuda_fp16.h>
#include <cstdint>
#include <math.h>

#define BATCH 512
#define NSEQ  128
#define DDIM  128
#define BIGF 1e30f

#define NCTA  512           // one batch per CTA; 3 CTAs resident per SM
#define NDIAG 255           // 2*NSEQ-1
#define PH    136           // fp16 staging pitch in halves (272 B/row; ldmatrix conflict-free)
#define DP_H  136           // diag pitch in halves (proven conflict-free)
#define BUF_WORDS (NSEQ * PH)                  // per-matrix halves = 17408
#define SM_DYN_BYTES (2 * BUF_WORDS * 2)       // 69632 B per CTA (x3 = 208.9KB/SM)
#define FILL_U4 (NDIAG * DP_H * 2 / 16)        // 4335 uint4

__device__ float g_dtw[BATCH];
__device__ int   g_ctr = 0;

__device__ __forceinline__ uint32_t smem_u32(const void* p) {
    uint32_t a;
    asm("{ .reg .u64 t; cvta.to.shared.u64 t, %1; cvt.u32.u64 %0, t; }" : "=r"(a) : "l"(p));
    return a;
}
__device__ __forceinline__ uint32_t f22h2(float lo, float hi) {
    uint32_t r;
    asm("cvt.rn.f16x2.f32 %0, %1, %2;" : "=r"(r) : "f"(hi), "f"(lo));
    return r;
}
__device__ __forceinline__ float2 h22f2(uint32_t u) {
    return __half22float2(*(__half2*)&u);
}
__device__ __forceinline__ void ldmx4(uint32_t* r, uint32_t addr) {
    asm volatile("ldmatrix.sync.aligned.m8n8.x4.shared.b16 {%0,%1,%2,%3}, [%4];"
                 : "=r"(r[0]), "=r"(r[1]), "=r"(r[2]), "=r"(r[3]) : "r"(addr));
}
// fp16 MMA with fp16 accumulator: C = 2 regs (4 halves)
__device__ __forceinline__ void mma_f16(uint32_t c[2], const uint32_t a[4],
                                        const uint32_t b[2]) {
    asm volatile(
        "mma.sync.aligned.m16n8k16.row.col.f16.f16.f16.f16 "
        "{%0,%1}, {%2,%3,%4,%5}, {%6,%7}, {%0,%1};\n"
        : "+r"(c[0]), "+r"(c[1])
        : "r"(a[0]), "r"(a[1]), "r"(a[2]), "r"(a[3]), "r"(b[0]), "r"(b[1]));
}

__global__ __launch_bounds__(256, 3) void fused_kernel(const float* __restrict__ X,
                                                       const float* __restrict__ Y,
                                                       float* __restrict__ out) {
    extern __shared__ __align__(16) __half smh[];
    __shared__ float xxs[NSEQ], yys[NSEQ];

    const int tid = threadIdx.x, w = tid >> 5, lane = tid & 31;
    const int b = blockIdx.x;

    const int qr = lane >> 2, qc = lane & 3;
    const int m0 = (w & 1) * 64, n0 = (w >> 1) * 32;

    __half* Xs = smh;                 // [128][136] fp16
    __half* Ys = smh + BUF_WORDS;     // [128][136] fp16
    __half* Dd = smh;                 // [255][136] fp16 (reuses buffer)

    // ldmatrix source addresses (constant across k; add 2*k0 bytes per step)
    const uint32_t xs_a = smem_u32(Xs);
    uint32_t aAddr[4], bAddr[2];
    #pragma unroll
    for (int mt = 0; mt < 4; mt++)
        aAddr[mt] = xs_a + (uint32_t)(((m0 + mt * 16 + (lane & 15)) * PH + (lane >> 4) * 8) * 2);
    const uint32_t ys_a = smem_u32(Ys);
    #pragma unroll
    for (int j = 0; j < 2; j++)
        bAddr[j] = ys_a + (uint32_t)(((n0 + (2 * j + (lane >> 4)) * 8 + (lane & 7)) * PH
                                      + ((lane >> 3) & 1) * 8) * 2);

    // ---- stage FULL X,Y as fp16 (deep-MLP coalesced LDG.128) ----
    const float* Xg = X + (size_t)b * NSEQ * DDIM;
    const float* Yg = Y + (size_t)b * NSEQ * DDIM;
    #pragma unroll 8
    for (int s = 0; s < 16; s++) {
        int idx = s * 256 + tid;            // 0..4095 float4s
        int r = idx >> 5, c4 = (idx & 31) << 2;
        float4 xv = *(const float4*)(Xg + r * DDIM + c4);
        float4 yv = *(const float4*)(Yg + r * DDIM + c4);
        *(uint2*)&Xs[r * PH + c4] = make_uint2(f22h2(xv.x, xv.y), f22h2(xv.z, xv.w));
        *(uint2*)&Ys[r * PH + c4] = make_uint2(f22h2(yv.x, yv.y), f22h2(yv.z, yv.w));
    }
    __syncthreads();

    // ---- norms from fp16 smem (1 row per thread), fp32 accumulate ----
    {
        int r = tid & 127;
        const __half* src = (tid < NSEQ) ? Xs : Ys;
        float s = 0.f;
        #pragma unroll
        for (int cc = 0; cc < DDIM; cc += 8) {
            uint4 v = *(const uint4*)&src[r * PH + cc];
            float2 f0 = h22f2(v.x), f1 = h22f2(v.y);
            float2 f2 = h22f2(v.z), f3 = h22f2(v.w);
            s = fmaf(f0.x, f0.x, fmaf(f0.y, f0.y, s));
            s = fmaf(f1.x, f1.x, fmaf(f1.y, f1.y, s));
            s = fmaf(f2.x, f2.x, fmaf(f2.y, f2.y, s));
            s = fmaf(f3.x, f3.x, fmaf(f3.y, f3.y, s));
        }
        if (tid < NSEQ) xxs[r] = s; else yys[r] = s;
    }

    // ---- fp16 HMMA mainloop: 8 K-steps of 16, fragments via ldmatrix.x4.
    //      fp16 accumulator: 32 acc regs -> fits 85-reg cap at 3 CTAs/SM. ----
    uint32_t acc[4][4][2];
    #pragma unroll
    for (int mt = 0; mt < 4; mt++)
        #pragma unroll
        for (int nt = 0; nt < 4; nt++) { acc[mt][nt][0] = 0u; acc[mt][nt][1] = 0u; }

    #pragma unroll 2
    for (int k0 = 0; k0 < DDIM; k0 += 16) {
        uint32_t bP[2][4];
        ldmx4(bP[0], bAddr[0] + 2 * k0);
        ldmx4(bP[1], bAddr[1] + 2 * k0);
        #pragma unroll
        for (int mt = 0; mt < 4; mt++) {
            uint32_t aF[4];
            ldmx4(aF, aAddr[mt] + 2 * k0);
            mma_f16(acc[mt][0], aF, &bP[0][0]);
            mma_f16(acc[mt][1], aF, &bP[0][2]);
            mma_f16(acc[mt][2], aF, &bP[1][0]);
            mma_f16(acc[mt][3], aF, &bP[1][2]);
        }
    }
    __syncthreads();   // staging reads done; buffer reusable; norms visible

    // ---- fill diag area with fp16 +inf (invalid cells self-mask in DP) ----
    {
        uint4 inf4 = make_uint4(0x7C007C00u, 0x7C007C00u, 0x7C007C00u, 0x7C007C00u);
        uint4* bv = (uint4*)smh;
        #pragma unroll
        for (int i = tid; i < FILL_U4; i += 256) bv[i] = inf4;
    }
    __syncthreads();

    // ---- epilogue: D = xx + yy - 2*xy -> fp16, diag-major ----
    #pragma unroll
    for (int mt = 0; mt < 4; mt++) {
        int i0 = m0 + mt * 16 + qr;
        float xv0 = xxs[i0], xv1 = xxs[i0 + 8];
        #pragma unroll
        for (int nt = 0; nt < 4; nt++) {
            int j0 = n0 + nt * 8 + 2 * qc;
            float yv0 = yys[j0], yv1 = yys[j0 + 1];
            float2 c01 = h22f2(acc[mt][nt][0]);   // row i0:   cols j0, j0+1
            float2 c23 = h22f2(acc[mt][nt][1]);   // row i0+8: cols j0, j0+1
            Dd[(i0 + j0)         * DP_H + j0]     = __float2half(xv0 + yv0 - 2.f * c01.x);
            Dd[(i0 + j0 + 1)     * DP_H + j0 + 1] = __float2half(xv0 + yv1 - 2.f * c01.y);
            Dd[(i0 + 8 + j0)     * DP_H + j0]     = __float2half(xv1 + yv0 - 2.f * c23.x);
            Dd[(i0 + 8 + j0 + 1) * DP_H + j0 + 1] = __float2half(xv1 + yv1 - 2.f * c23.y);
        }
    }
    __syncthreads();

    // ---- soft-DTW DP: warp 0 only (skewed wavefront, proven R9-R12) ----
    if (w == 0) {
        const int l = lane;
        float A0 = BIGF, A1 = BIGF, A2 = BIGF, A3 = BIGF;
        float B0 = BIGF, B1 = BIGF, B2 = BIGF, B3 = BIGF;
        float uE = BIGF, uO = BIGF;
        const int zstep = (l == 0) ? 0 : -1;

        const __half* base = (const __half*)Dd + 4 * l;
        auto ldD = [&](int s_) -> uint2 {
            int k = s_ - l;
            k = k < 0 ? 0 : (k > NDIAG - 1 ? NDIAG - 1 : k);
            return *(const uint2*)(base + k * DP_H);
        };
        uint2 q0 = ldD(0), q1 = ldD(1);

        #pragma unroll 1
        for (int s = 0; s < 286; s += 2) {
            float recv = __shfl_up_sync(0xffffffffu, A3, 1);
            recv = (l == 0) ? BIGF : recv;
            uint2 dq = q0; q0 = ldD(s + 2);
            float2 f01 = h22f2(dq.x);
            float2 f23 = h22f2(dq.y);
            {
                float dg0 = (s == zstep) ? 0.f : uE;
                float t0 = f01.x + fminf(fminf(dg0, uO), A0);
                float t1 = f01.y + fminf(fminf(B0, A0), A1);
                float t2 = f23.x + fminf(fminf(B1, A1), A2);
                float t3 = f23.y + fminf(fminf(B2, A2), A3);
                B0 = t0; B1 = t1; B2 = t2; B3 = t3;
            }
            uE = recv;

            recv = __shfl_up_sync(0xffffffffu, B3, 1);
            recv = (l == 0) ? BIGF : recv;
            dq = q1; q1 = ldD(s + 3);
            f01 = h22f2(dq.x);
            f23 = h22f2(dq.y);
            {
                float t0 = f01.x + fminf(fminf(uO, uE), B0);
                float t1 = f01.y + fminf(fminf(A0, B0), B1);
                float t2 = f23.x + fminf(fminf(A1, B1), B2);
                float t3 = f23.y + fminf(fminf(A2, B2), B3);
                A0 = t0; A1 = t1; A2 = t2; A3 = t3;
            }
            uO = recv;
        }
        if (l == 31) g_dtw[b] = A3;   // R[127][127] (k = 254)
    }
    __syncthreads();

    if (tid == 0) {
        __threadfence();
        if (atomicAdd(&g_ctr, 1) == NCTA - 1) {
            __threadfence();
            // deterministic fixed-order reduction of g_dtw[0..511]
            float a0 = 0.f, a1 = 0.f, a2 = 0.f, a3 = 0.f;
            float a4 = 0.f, a5 = 0.f, a6 = 0.f, a7 = 0.f;
            for (int i = 0; i < BATCH; i += 32) {
                float4 v0 = *(const float4*)&g_dtw[i];
                float4 v1 = *(const float4*)&g_dtw[i + 4];
                float4 v2 = *(const float4*)&g_dtw[i + 8];
                float4 v3 = *(const float4*)&g_dtw[i + 12];
                float4 v4 = *(const float4*)&g_dtw[i + 16];
                float4 v5 = *(const float4*)&g_dtw[i + 20];
                float4 v6 = *(const float4*)&g_dtw[i + 24];
                float4 v7 = *(const float4*)&g_dtw[i + 28];
                a0 += (v0.x + v0.y) + (v0.z + v0.w);
                a1 += (v1.x + v1.y) + (v1.z + v1.w);
                a2 += (v2.x + v2.y) + (v2.z + v2.w);
                a3 += (v3.x + v3.y) + (v3.z + v3.w);
                a4 += (v4.x + v4.y) + (v4.z + v4.w);
                a5 += (v5.x + v5.y) + (v5.z + v5.w);
                a6 += (v6.x + v6.y) + (v6.z + v6.w);
                a7 += (v7.x + v7.y) + (v7.z + v7.w);
            }
            float s = ((a0 + a1) + (a2 + a3)) + ((a4 + a5) + (a6 + a7));
            float E = s * (1.0f / (float)BATCH);
            out[0] = E;
            out[1] = 10.0f * sqrtf(E + 1e-10f);
            g_ctr = 0;   // reset for graph replay
        }
    }
}

extern "C" void kernel_launch(void* const* d_in, const int* in_sizes, int n_in,
                              void* d_out, int out_size) {
    const float* X = (const float*)d_in[0];   // outputs
    const float* Y = (const float*)d_in[1];   // targets
    float* out = (float*)d_out;

    cudaFuncSetAttribute(fused_kernel, cudaFuncAttributeMaxDynamicSharedMemorySize,
                         SM_DYN_BYTES);

    fused_kernel<<<NCTA, 256, SM_DYN_BYTES>>>(X, Y, out);
}